// round 14
// baseline (speedup 1.0000x reference)
#include <cuda_runtime.h>
#include <cuda_fp16.h>
#include <math_constants.h>
#include <cstdint>

#define BATCH 32
#define CDIM  1024
#define CI    512
#define NPOS  784

// -------- scratch (device globals) --------
__device__ __align__(16) __half g_Wh[(size_t)CDIM * CDIM];          // W fp16 (theta rows 0..511, phi 512..1023)
__device__ __align__(16) __half g_Xt[(size_t)BATCH * NPOS * CDIM];  // X^T fp16 [b][n][c]
__device__ __align__(16) __half g_Th[(size_t)BATCH * NPOS * CI];    // theta^T fp16 [b][n][k]
__device__ __align__(16) __half g_Ph[(size_t)BATCH * NPOS * CI];    // phi^T fp16
__device__ __align__(16) __half g_E[(size_t)BATCH * NPOS * NPOS];   // exp(f - pmax[row,cb]) fp16
__device__ float g_pmax[BATCH * 7 * NPOS];   // per-colblock row max
__device__ float g_psum[BATCH * 7 * NPOS];   // per-colblock row sumexp
__device__ float g_abar[BATCH * NPOS];
__device__ float g_xw[BATCH * CDIM];
__device__ float g_xbar[BATCH * CDIM];

// -------- helpers --------
__device__ __forceinline__ uint32_t smem_u32(const void* p) {
    uint32_t a;
    asm("{ .reg .u64 t; cvta.to.shared.u64 t, %1; cvt.u32.u64 %0, t; }" : "=r"(a) : "l"(p));
    return a;
}
__device__ __forceinline__ void cp16(uint32_t dst, const void* src) {
    asm volatile("cp.async.cg.shared.global [%0], [%1], 16;" :: "r"(dst), "l"(src) : "memory");
}
#define CP_COMMIT() asm volatile("cp.async.commit_group;" ::: "memory")
#define CP_WAIT_1() asm volatile("cp.async.wait_group 1;" ::: "memory")
#define CP_WAIT_2() asm volatile("cp.async.wait_group 2;" ::: "memory")

__device__ __forceinline__ void ldsm_x4(uint32_t (&r)[4], uint32_t a) {
    asm volatile("ldmatrix.sync.aligned.m8n8.x4.shared.b16 {%0,%1,%2,%3}, [%4];"
                 : "=r"(r[0]), "=r"(r[1]), "=r"(r[2]), "=r"(r[3]) : "r"(a));
}
__device__ __forceinline__ void ldsm_x2(uint32_t& r0, uint32_t& r1, uint32_t a) {
    asm volatile("ldmatrix.sync.aligned.m8n8.x2.shared.b16 {%0,%1}, [%2];"
                 : "=r"(r0), "=r"(r1) : "r"(a));
}
__device__ __forceinline__ void mma16816(float* c, const uint32_t* a, const uint32_t* b) {
    asm volatile(
        "mma.sync.aligned.m16n8k16.row.col.f32.f16.f16.f32 "
        "{%0,%1,%2,%3}, {%4,%5,%6,%7}, {%8,%9}, {%0,%1,%2,%3};"
        : "+f"(c[0]), "+f"(c[1]), "+f"(c[2]), "+f"(c[3])
        : "r"(a[0]), "r"(a[1]), "r"(a[2]), "r"(a[3]), "r"(b[0]), "r"(b[1]));
}

// ===========================================================================
// conversions
// ===========================================================================
__global__ __launch_bounds__(256) void convert_W_kernel(
    const float* __restrict__ Wth, const float* __restrict__ Wph)
{
    int i = blockIdx.x * 256 + threadIdx.x;
    float w = (i < CI * CDIM) ? Wth[i] : Wph[i - CI * CDIM];
    g_Wh[i] = __float2half(w);
    if (i < BATCH * NPOS) g_abar[i] = 0.f;
    if (i < BATCH * CDIM) { g_xw[i] = 0.f; g_xbar[i] = 0.f; }
}

// X [b][c][n] fp32 -> X^T [b][n][c] fp16; 64x64 tiles, vectorized IO
#define CX_PITCH 72
__global__ __launch_bounds__(256) void convert_X_kernel(const float* __restrict__ x)
{
    __shared__ __half tile[64 * CX_PITCH];
    const int b   = blockIdx.z;
    const int c0  = blockIdx.y * 64;
    const int n0  = blockIdx.x * 64;
    const int tid = threadIdx.x;

    #pragma unroll
    for (int i = 0; i < 4; i++) {
        int t = tid + i * 256;
        int c = t >> 4, nq = t & 15;
        int n = n0 + nq * 4;
        float4 v = make_float4(0.f, 0.f, 0.f, 0.f);
        if (n < NPOS)
            v = *reinterpret_cast<const float4*>(
                x + ((size_t)b * CDIM + c0 + c) * NPOS + n);
        __half2 h01 = __floats2half2_rn(v.x, v.y);
        __half2 h23 = __floats2half2_rn(v.z, v.w);
        uint2 pk;
        pk.x = *reinterpret_cast<uint32_t*>(&h01);
        pk.y = *reinterpret_cast<uint32_t*>(&h23);
        *reinterpret_cast<uint2*>(tile + c * CX_PITCH + nq * 4) = pk;
    }
    __syncthreads();
    #pragma unroll
    for (int i = 0; i < 2; i++) {
        int t = tid + i * 256;
        int n = t >> 3, cq = t & 7;
        if (n0 + n < NPOS) {
            __align__(16) __half h8[8];
            #pragma unroll
            for (int k = 0; k < 8; k++)
                h8[k] = tile[(cq * 8 + k) * CX_PITCH + n];
            *reinterpret_cast<uint4*>(
                g_Xt + ((size_t)b * NPOS + n0 + n) * CDIM + c0 + cq * 8) =
                *reinterpret_cast<const uint4*>(h8);
        }
    }
}

// ===========================================================================
// GEMM1 (warp MMA, fp16): C[m][n] = sum_k W[m][k] X^T[n][k]
// CTA tile 128x112, 4 warps (2M x 2N), warp tile 64x56.
// 3-stage cp.async pipeline (K=32 stages).
// ===========================================================================
#define G1_BOFF  10240           // A: 128 rows * 80B
#define G1_STAGE 19200           // + B: 112 rows * 80B
#define G1_SMEM  57600
#define G1_EPITCH 144            // halves per n-row in epilogue bounce

__global__ __launch_bounds__(128, 3) void gemm1_mma(
    const float* __restrict__ bth, const float* __restrict__ bph)
{
    extern __shared__ char smc[];
    const uint32_t sbase = smem_u32(smc);
    const int tid  = threadIdx.x;
    const int lane = tid & 31;
    const int wid  = tid >> 5;           // 0..3
    const int wm   = wid >> 1;           // 0..1  (M, 64 rows)
    const int wn   = wid & 1;            // 0..1  (N, 56 cols)
    const int b    = blockIdx.z;
    const int m0   = blockIdx.y * 128;
    const int n0   = blockIdx.x * 112;

    float acc[28][4];
    #pragma unroll
    for (int i = 0; i < 28; i++)
        #pragma unroll
        for (int j = 0; j < 4; j++) acc[i][j] = 0.f;

    auto issue = [&](int kt, int buf) {
        const int k0 = kt * 32;
        const uint32_t st = sbase + buf * G1_STAGE;
        #pragma unroll
        for (int i = 0; i < 4; i++) {           // A: 512 tasks
            int t = tid + i * 128;
            int row = t >> 2, ch = t & 3;
            const __half* src = g_Wh + (size_t)(m0 + row) * CDIM + k0 + ch * 8;
            cp16(st + row * 80 + ch * 16, src);
        }
        #pragma unroll
        for (int i = 0; i < 4; i++) {           // B: 448 tasks
            int t = tid + i * 128;
            if (t < 448) {
                int row = t >> 2, ch = t & 3;
                const __half* src = g_Xt
                    + ((size_t)b * NPOS + n0 + row) * CDIM + k0 + ch * 8;
                cp16(st + G1_BOFF + row * 80 + ch * 16, src);
            }
        }
        CP_COMMIT();
    };

    issue(0, 0);
    issue(1, 1);
    issue(2, 2);

    const int arow = lane & 15;
    const int ach  = lane >> 4;
    const int brow = ((lane >> 4) << 3) + (lane & 7);
    const int bch  = (lane >> 3) & 1;
    const int brow2 = (lane & 15) & 7;
    const int bch2  = ((lane & 15) >> 3) & 1;

    int buf = 0, pbuf = 0;
    for (int kt = 0; kt < 32; kt++) {
        CP_WAIT_2();
        __syncthreads();
        const uint32_t st = sbase + buf * G1_STAGE;
        #pragma unroll
        for (int s = 0; s < 2; s++) {
            uint32_t ah[4][4], bb[7][2];
            #pragma unroll
            for (int p = 0; p < 3; p++) {
                uint32_t ba = st + G1_BOFF + (wn * 56 + p * 16 + brow) * 80 + (s * 2 + bch) * 16;
                uint32_t r[4]; ldsm_x4(r, ba);
                bb[p*2][0] = r[0]; bb[p*2][1] = r[1];
                bb[p*2+1][0] = r[2]; bb[p*2+1][1] = r[3];
            }
            ldsm_x2(bb[6][0], bb[6][1],
                    st + G1_BOFF + (wn * 56 + 48 + brow2) * 80 + (s * 2 + bch2) * 16);
            #pragma unroll
            for (int i = 0; i < 4; i++) {
                uint32_t aa = st + (wm * 64 + i * 16 + arow) * 80 + (s * 2 + ach) * 16;
                ldsm_x4(ah[i], aa);
            }
            #pragma unroll
            for (int i = 0; i < 4; i++)
                #pragma unroll
                for (int j = 0; j < 7; j++)
                    mma16816(acc[i*7+j], ah[i], bb[j]);
        }
        __syncthreads();
        if (kt + 3 < 32) issue(kt + 3, pbuf); else CP_COMMIT();
        buf  = (buf == 2)  ? 0 : buf + 1;
        pbuf = (pbuf == 2) ? 0 : pbuf + 1;
    }

    // ---- epilogue: fp16 bounce [n][ch] pitch 144, then uint4 biased stores
    __syncthreads();
    __half* eb = reinterpret_cast<__half*>(smc);
    #pragma unroll
    for (int i = 0; i < 4; i++)
        #pragma unroll
        for (int j = 0; j < 7; j++) {
            int ch  = wm * 64 + i * 16 + (lane >> 2);
            int col = wn * 56 + j * 8 + (lane & 3) * 2;
            eb[col * G1_EPITCH + ch]           = __float2half(acc[i*7+j][0]);
            eb[(col + 1) * G1_EPITCH + ch]     = __float2half(acc[i*7+j][1]);
            eb[col * G1_EPITCH + ch + 8]       = __float2half(acc[i*7+j][2]);
            eb[(col + 1) * G1_EPITCH + ch + 8] = __float2half(acc[i*7+j][3]);
        }
    __syncthreads();

    const bool isTheta = (m0 < CI);
    __half* dst = isTheta ? g_Th : g_Ph;
    const int ch0g = isTheta ? m0 : (m0 - CI);
    const float* bias = isTheta ? bth : bph;

    #pragma unroll
    for (int it = 0; it < 14; it++) {
        int t  = tid + it * 128;       // 0..1791
        int cg = t & 15, n = t >> 4;
        int chl = cg * 8;
        uint4 raw = *reinterpret_cast<const uint4*>(eb + n * G1_EPITCH + chl);
        const __half* rh = reinterpret_cast<const __half*>(&raw);
        __align__(16) __half h8[8];
        #pragma unroll
        for (int k = 0; k < 8; k++)
            h8[k] = __float2half(__half2float(rh[k]) + bias[ch0g + chl + k]);
        size_t off = ((size_t)b * NPOS + n0 + n) * CI + ch0g + chl;
        *reinterpret_cast<uint4*>(dst + off) = *reinterpret_cast<const uint4*>(h8);
    }
}

// ===========================================================================
// GEMM2 (warp MMA, fp16): F[n][m] = sum_k Th[n][k] Ph[m][k]
// CTA tile 128(n, clamped) x 112(m), 8 warps (4M x 2N), warp 32x56.
// K=64 stages, 2-stage pipeline (pitch 144B).
// Epilogue: register-resident row stats, exp in regs, fp16 E bounce.
// ===========================================================================
#define G2_PITCH 144
#define G2_BOFF  18432           // A: 128 rows * 144B
#define G2_STAGE 34560           // + B: 112 rows * 144B
#define G2_SMEM  69120
#define G2_EPH   120             // halves per row in fp16 E bounce

__global__ __launch_bounds__(256, 2) void gemm2_mma()
{
    extern __shared__ char smc[];
    const uint32_t sbase = smem_u32(smc);
    const int tid  = threadIdx.x;
    const int lane = tid & 31;
    const int wid  = tid >> 5;           // 0..7
    const int wm   = wid >> 1;           // 0..3  (rows n, 32 each)
    const int wn   = wid & 1;            // 0..1  (cols m, 56 each)
    const int b    = blockIdx.z;
    const int n0   = blockIdx.y * 128;   // rows (theta), padded range
    const int cbx  = blockIdx.x;         // col block 0..6
    const int mb0  = cbx * 112;          // cols (phi)

    float acc[14][4];
    #pragma unroll
    for (int i = 0; i < 14; i++)
        #pragma unroll
        for (int j = 0; j < 4; j++) acc[i][j] = 0.f;

    auto issue = [&](int kt, int buf) {
        const int k0 = kt * 64;
        const uint32_t st = sbase + buf * G2_STAGE;
        #pragma unroll
        for (int i = 0; i < 4; i++) {    // A: 1024 tasks, clamp row
            int t = tid + i * 256;
            int row = t >> 3, ch = t & 7;
            int gn = n0 + row; if (gn > NPOS - 1) gn = NPOS - 1;
            const __half* asrc = g_Th
                + ((size_t)b * NPOS + gn) * CI + k0 + ch * 8;
            cp16(st + row * G2_PITCH + ch * 16, asrc);
        }
        #pragma unroll
        for (int i = 0; i < 4; i++) {    // B: 896 tasks
            int t = tid + i * 256;
            if (t < 896) {
                int row = t >> 3, ch = t & 7;
                const __half* bsrc = g_Ph
                    + ((size_t)b * NPOS + mb0 + row) * CI + k0 + ch * 8;
                cp16(st + G2_BOFF + row * G2_PITCH + ch * 16, bsrc);
            }
        }
        CP_COMMIT();
    };

    issue(0, 0);
    issue(1, 1);

    const int arow = lane & 15;
    const int ach  = lane >> 4;
    const int brow = ((lane >> 4) << 3) + (lane & 7);
    const int bch  = (lane >> 3) & 1;
    const int brow2 = (lane & 15) & 7;
    const int bch2  = ((lane & 15) >> 3) & 1;

    int buf = 0;
    for (int kt = 0; kt < 8; kt++) {
        CP_WAIT_1();
        __syncthreads();
        const uint32_t st = sbase + buf * G2_STAGE;
        #pragma unroll
        for (int s = 0; s < 4; s++) {
            uint32_t ah[2][4], bb[7][2];
            #pragma unroll
            for (int i = 0; i < 2; i++) {
                uint32_t aa = st + (wm * 32 + i * 16 + arow) * G2_PITCH + (s * 2 + ach) * 16;
                ldsm_x4(ah[i], aa);
            }
            #pragma unroll
            for (int p = 0; p < 3; p++) {
                uint32_t ba = st + G2_BOFF + (wn * 56 + p * 16 + brow) * G2_PITCH + (s * 2 + bch) * 16;
                uint32_t r[4]; ldsm_x4(r, ba);
                bb[p*2][0] = r[0]; bb[p*2][1] = r[1];
                bb[p*2+1][0] = r[2]; bb[p*2+1][1] = r[3];
            }
            ldsm_x2(bb[6][0], bb[6][1],
                    st + G2_BOFF + (wn * 56 + 48 + brow2) * G2_PITCH + (s * 2 + bch2) * 16);
            #pragma unroll
            for (int i = 0; i < 2; i++)
                #pragma unroll
                for (int j = 0; j < 7; j++)
                    mma16816(acc[i*7+j], ah[i], bb[j]);
        }
        __syncthreads();
        if (kt + 2 < 8) issue(kt + 2, buf); else CP_COMMIT();
        buf ^= 1;
    }

    // ======== epilogue: register-resident stats + fp16 E bounce ========
    __syncthreads();
    __half* ebh  = reinterpret_cast<__half*>(smc);                 // [128][120] halves
    float* rmax2 = reinterpret_cast<float*>(smc + 30720);          // [128][2]
    float* psum2 = reinterpret_cast<float*>(smc + 30720 + 1024);   // [128][2]

    const int r = lane >> 2;   // 0..7
    const int q = lane & 3;    // 0..3

    float rmx[4];
    #pragma unroll
    for (int i = 0; i < 2; i++) {
        float m0 = -CUDART_INF_F, m1 = -CUDART_INF_F;
        #pragma unroll
        for (int j = 0; j < 7; j++) {
            m0 = fmaxf(m0, fmaxf(acc[i*7+j][0], acc[i*7+j][1]));
            m1 = fmaxf(m1, fmaxf(acc[i*7+j][2], acc[i*7+j][3]));
        }
        #pragma unroll
        for (int o = 1; o < 4; o <<= 1) {
            m0 = fmaxf(m0, __shfl_xor_sync(0xffffffffu, m0, o));
            m1 = fmaxf(m1, __shfl_xor_sync(0xffffffffu, m1, o));
        }
        rmx[i*2]   = m0;
        rmx[i*2+1] = m1;
    }
    if (q == 0) {
        #pragma unroll
        for (int k = 0; k < 4; k++) {
            int row = wm * 32 + (k >> 1) * 16 + (k & 1) * 8 + r;
            rmax2[row * 2 + wn] = rmx[k];
        }
    }
    __syncthreads();

    float frmx[4];
    #pragma unroll
    for (int k = 0; k < 4; k++) {
        int row = wm * 32 + (k >> 1) * 16 + (k & 1) * 8 + r;
        frmx[k] = fmaxf(rmax2[row * 2], rmax2[row * 2 + 1]);
    }

    float ps[4] = {0.f, 0.f, 0.f, 0.f};
    #pragma unroll
    for (int i = 0; i < 2; i++) {
        #pragma unroll
        for (int j = 0; j < 7; j++) {
            int col  = wn * 56 + j * 8 + q * 2;
            int row0 = wm * 32 + i * 16 + r;
            float e0 = __expf(acc[i*7+j][0] - frmx[i*2]);
            float e1 = __expf(acc[i*7+j][1] - frmx[i*2]);
            float e2 = __expf(acc[i*7+j][2] - frmx[i*2+1]);
            float e3 = __expf(acc[i*7+j][3] - frmx[i*2+1]);
            ps[i*2]   += e0 + e1;
            ps[i*2+1] += e2 + e3;
            __half2 h01 = __floats2half2_rn(e0, e1);
            __half2 h23 = __floats2half2_rn(e2, e3);
            *reinterpret_cast<__half2*>(ebh + row0 * G2_EPH + col)       = h01;
            *reinterpret_cast<__half2*>(ebh + (row0 + 8) * G2_EPH + col) = h23;
        }
    }
    #pragma unroll
    for (int k = 0; k < 4; k++)
        #pragma unroll
        for (int o = 1; o < 4; o <<= 1)
            ps[k] += __shfl_xor_sync(0xffffffffu, ps[k], o);
    if (q == 0) {
        #pragma unroll
        for (int k = 0; k < 4; k++) {
            int row = wm * 32 + (k >> 1) * 16 + (k & 1) * 8 + r;
            psum2[row * 2 + wn] = ps[k];
        }
    }
    __syncthreads();

    if (tid < 128 && n0 + tid < NPOS) {
        int o = (b * 7 + cbx) * NPOS + n0 + tid;
        g_pmax[o] = fmaxf(rmax2[tid * 2], rmax2[tid * 2 + 1]);
        g_psum[o] = psum2[tid * 2] + psum2[tid * 2 + 1];
    }

    #pragma unroll
    for (int i = 0; i < 7; i++) {
        int t = tid + i * 256;          // 0..1791
        int row = t / 14, cg = t % 14;
        if (n0 + row < NPOS) {
            uint4 v = *reinterpret_cast<const uint4*>(ebh + row * G2_EPH + cg * 8);
            *reinterpret_cast<uint4*>(
                g_E + ((size_t)b * NPOS + n0 + row) * NPOS + mb0 + cg * 8) = v;
        }
    }
}

// ===========================================================================
// colsum (vectorized, inline combine):
// a_bar[b][m] += sum_n E[n][m] * w[n][cb(m)]; thread handles 4 adjacent m.
// grid (1, 14 n-chunks of 56, BATCH), block 196.
// ===========================================================================
__global__ __launch_bounds__(196) void colsum_kernel()
{
    const int b  = blockIdx.z;
    const int n0 = blockIdx.y * 56;
    const int t  = threadIdx.x;          // 0..195
    const int m4 = t * 4;                // 0..780
    const int cbx = m4 / 112;            // 0..6 (no 4-group crosses a 112 boundary)

    __shared__ float sw[7][56];
    if (t < 56) {
        int n = n0 + t;
        float pm[7];
        float mx = -CUDART_INF_F;
        #pragma unroll
        for (int cb = 0; cb < 7; cb++) {
            pm[cb] = g_pmax[(b * 7 + cb) * NPOS + n];
            mx = fmaxf(mx, pm[cb]);
        }
        float s = 0.f;
        #pragma unroll
        for (int cb = 0; cb < 7; cb++)
            s += g_psum[(b * 7 + cb) * NPOS + n] * __expf(pm[cb] - mx);
        float inv = 1.f / (s * (float)NPOS);
        #pragma unroll
        for (int cb = 0; cb < 7; cb++)
            sw[cb][t] = __expf(pm[cb] - mx) * inv;
    }
    __syncthreads();

    const __half* __restrict__ Eb = g_E + ((size_t)b * NPOS + n0) * NPOS + m4;
    float a0 = 0.f, a1 = 0.f, a2 = 0.f, a3 = 0.f;
    #pragma unroll 8
    for (int j = 0; j < 56; j++) {
        uint2 v = *reinterpret_cast<const uint2*>(Eb + (size_t)j * NPOS);
        __half2 h01 = *reinterpret_cast<__half2*>(&v.x);
        __half2 h23 = *reinterpret_cast<__half2*>(&v.y);
        float2 f01 = __half22float2(h01);
        float2 f23 = __half22float2(h23);
        float w = sw[cbx][j];
        a0 = fmaf(f01.x, w, a0);
        a1 = fmaf(f01.y, w, a1);
        a2 = fmaf(f23.x, w, a2);
        a3 = fmaf(f23.y, w, a3);
    }
    atomicAdd(&g_abar[b * NPOS + m4 + 0], a0);
    atomicAdd(&g_abar[b * NPOS + m4 + 1], a1);
    atomicAdd(&g_abar[b * NPOS + m4 + 2], a2);
    atomicAdd(&g_abar[b * NPOS + m4 + 3], a3);
}

// xw[b][c] += sum_n Xt[b][n][c]*abar[n];  xbar[b][c] += sum_n Xt[b][n][c]/784
__global__ __launch_bounds__(256) void xw_kernel()
{
    const int b   = blockIdx.z;
    const int c0  = blockIdx.x * 512;
    const int n0  = blockIdx.y * 98;
    const int tid = threadIdx.x;

    __shared__ float sa[98];
    if (tid < 98) sa[tid] = g_abar[b * NPOS + n0 + tid];
    __syncthreads();

    const __half2* __restrict__ Xt2 = reinterpret_cast<const __half2*>(
        g_Xt + ((size_t)b * NPOS + n0) * CDIM + c0) + tid;

    float d0 = 0.f, d1 = 0.f, s0 = 0.f, s1 = 0.f;
    #pragma unroll 7
    for (int n = 0; n < 98; n++) {
        __half2 h = Xt2[(size_t)n * (CDIM / 2)];
        float2 f = __half22float2(h);
        float a = sa[n];
        d0 = fmaf(f.x, a, d0);
        d1 = fmaf(f.y, a, d1);
        s0 += f.x;
        s1 += f.y;
    }
    int c = c0 + tid * 2;
    atomicAdd(&g_xw[b * CDIM + c],       d0);
    atomicAdd(&g_xw[b * CDIM + c + 1],   d1);
    atomicAdd(&g_xbar[b * CDIM + c],     s0 * (1.f / (float)NPOS));
    atomicAdd(&g_xbar[b * CDIM + c + 1], s1 * (1.f / (float)NPOS));
}

// ===========================================================================
// fused tail: ybar -> pooled(BN+res) -> h -> out, one CTA per batch
// ===========================================================================
__global__ __launch_bounds__(256) void tail_kernel(
    const float* __restrict__ Wg, const float* __restrict__ bg,
    const float* __restrict__ Ww, const float* __restrict__ bw,
    const float* __restrict__ gamma, const float* __restrict__ beta,
    const float* __restrict__ bmean, const float* __restrict__ bvar,
    const float* __restrict__ W1, const float* __restrict__ b1,
    const float* __restrict__ W2, const float* __restrict__ b2,
    const float* __restrict__ xface, float* __restrict__ out)
{
    const int b    = blockIdx.x;
    const int tid  = threadIdx.x;
    const int lane = tid & 31;
    const int wid  = tid >> 5;

    __shared__ float sx[CDIM];   // xw
    __shared__ float sy[CI];     // ybar
    __shared__ float sp[CDIM];   // pooled
    __shared__ float sh[CI];     // h

    for (int k = tid; k < CDIM; k += 256) sx[k] = g_xw[b * CDIM + k];
    __syncthreads();

    // ybar[i] = Wg[i][:]·sx + bg[i]
    for (int i = wid; i < CI; i += 8) {
        const float* w = Wg + (size_t)i * CDIM;
        float d = 0.f;
        #pragma unroll 8
        for (int k = lane; k < CDIM; k += 32) d = fmaf(w[k], sx[k], d);
        #pragma unroll
        for (int o = 16; o; o >>= 1) d += __shfl_xor_sync(0xffffffffu, d, o);
        if (lane == 0) sy[i] = d + bg[i];
    }
    __syncthreads();

    // pooled[c] = inv*(Ww[c]·sy + bw) + (beta - mean*inv) + xbar
    for (int c = wid; c < CDIM; c += 8) {
        const float* w = Ww + (size_t)c * CI;
        float d = 0.f;
        #pragma unroll 8
        for (int k = lane; k < CI; k += 32) d = fmaf(w[k], sy[k], d);
        #pragma unroll
        for (int o = 16; o; o >>= 1) d += __shfl_xor_sync(0xffffffffu, d, o);
        if (lane == 0) {
            float inv = gamma[c] * rsqrtf(bvar[c] + 1e-5f);
            sp[c] = inv * (d + bw[c]) + (beta[c] - bmean[c] * inv)
                  + g_xbar[b * CDIM + c];
        }
    }
    __syncthreads();

    // h[j] = W1[j]·sp + b1[j]
    for (int j = wid; j < CI; j += 8) {
        const float* w = W1 + (size_t)j * CDIM;
        float d = 0.f;
        #pragma unroll 8
        for (int k = lane; k < CDIM; k += 32) d = fmaf(w[k], sp[k], d);
        #pragma unroll
        for (int o = 16; o; o >>= 1) d += __shfl_xor_sync(0xffffffffu, d, o);
        if (lane == 0) sh[j] = d + b1[j];
    }
    __syncthreads();

    // out[o] = W2[o][0:512]·h + W2[o][512:1024]·xface + b2[o]
    if (wid < 2) {
        const float* w = W2 + (size_t)wid * CDIM;
        float d = 0.f;
        #pragma unroll 8
        for (int k = lane; k < CDIM; k += 32) {
            float v = (k < CI) ? sh[k] : xface[b * CI + (k - CI)];
            d = fmaf(w[k], v, d);
        }
        #pragma unroll
        for (int o = 16; o; o >>= 1) d += __shfl_xor_sync(0xffffffffu, d, o);
        if (lane == 0) out[b * 2 + wid] = d + b2[wid];
    }
}

// ===========================================================================
extern "C" void kernel_launch(void* const* d_in, const int* in_sizes, int n_in,
                              void* d_out, int out_size)
{
    const float* x_body = (const float*)d_in[0];
    const float* x_face = (const float*)d_in[1];
    const float* Wg     = (const float*)d_in[2];
    const float* bg     = (const float*)d_in[3];
    const float* Wth    = (const float*)d_in[4];
    const float* bth    = (const float*)d_in[5];
    const float* Wph    = (const float*)d_in[6];
    const float* bph    = (const float*)d_in[7];
    const float* Ww     = (const float*)d_in[8];
    const float* bw     = (const float*)d_in[9];
    const float* gamma  = (const float*)d_in[10];
    const float* beta   = (const float*)d_in[11];
    const float* bmean  = (const float*)d_in[12];
    const float* bvar   = (const float*)d_in[13];
    const float* W1     = (const float*)d_in[14];
    const float* b1     = (const float*)d_in[15];
    const float* W2     = (const float*)d_in[16];
    const float* b2     = (const float*)d_in[17];
    float* out = (float*)d_out;

    cudaFuncSetAttribute(gemm1_mma, cudaFuncAttributeMaxDynamicSharedMemorySize, G1_SMEM);
    cudaFuncSetAttribute(gemm2_mma, cudaFuncAttributeMaxDynamicSharedMemorySize, G2_SMEM);

    convert_W_kernel<<<(CDIM * CDIM) / 256, 256>>>(Wth, Wph);
    convert_X_kernel<<<dim3((NPOS + 63) / 64, CDIM / 64, BATCH), 256>>>(x_body);

    gemm1_mma<<<dim3(NPOS / 112, CDIM / 128, BATCH), 128, G1_SMEM>>>(bth, bph);
    gemm2_mma<<<dim3(NPOS / 112, (NPOS + 127) / 128, BATCH), 256, G2_SMEM>>>();

    colsum_kernel<<<dim3(1, 14, BATCH), 196>>>();
    xw_kernel<<<dim3(2, 8, BATCH), 256>>>();
    tail_kernel<<<BATCH, 256>>>(Wg, bg, Ww, bw, gamma, beta, bmean, bvar,
                                W1, b1, W2, b2, x_face, out);
}

// round 15
// speedup vs baseline: 2.0199x; 2.0199x over previous
#include <cuda_runtime.h>
#include <cuda_fp16.h>
#include <math_constants.h>
#include <cstdint>

#define BATCH 32
#define CDIM  1024
#define CI    512
#define NPOS  784

// -------- scratch (device globals) --------
__device__ __align__(16) __half g_Wh[(size_t)CDIM * CDIM];          // W fp16 (theta rows 0..511, phi 512..1023)
__device__ __align__(16) __half g_Xt[(size_t)BATCH * NPOS * CDIM];  // X^T fp16 [b][n][c]
__device__ __align__(16) __half g_Th[(size_t)BATCH * NPOS * CI];    // theta^T fp16 [b][n][k]
__device__ __align__(16) __half g_Ph[(size_t)BATCH * NPOS * CI];    // phi^T fp16
__device__ __align__(16) __half g_E[(size_t)BATCH * NPOS * NPOS];   // exp(f - pmax[row,cb]) fp16
__device__ float g_pmax[BATCH * 7 * NPOS];   // per-colblock row max
__device__ float g_psum[BATCH * 7 * NPOS];   // per-colblock row sumexp
__device__ float g_abar[BATCH * NPOS];
__device__ float g_xw[BATCH * CDIM];
__device__ float g_xbar[BATCH * CDIM];
__device__ float g_ybar[BATCH * CI];
__device__ float g_pooled[BATCH * CDIM];
__device__ float g_h[BATCH * CI];

// -------- helpers --------
__device__ __forceinline__ uint32_t smem_u32(const void* p) {
    uint32_t a;
    asm("{ .reg .u64 t; cvta.to.shared.u64 t, %1; cvt.u32.u64 %0, t; }" : "=r"(a) : "l"(p));
    return a;
}
__device__ __forceinline__ void cp16(uint32_t dst, const void* src) {
    asm volatile("cp.async.cg.shared.global [%0], [%1], 16;" :: "r"(dst), "l"(src) : "memory");
}
#define CP_COMMIT() asm volatile("cp.async.commit_group;" ::: "memory")
#define CP_WAIT_1() asm volatile("cp.async.wait_group 1;" ::: "memory")
#define CP_WAIT_2() asm volatile("cp.async.wait_group 2;" ::: "memory")

__device__ __forceinline__ void ldsm_x4(uint32_t (&r)[4], uint32_t a) {
    asm volatile("ldmatrix.sync.aligned.m8n8.x4.shared.b16 {%0,%1,%2,%3}, [%4];"
                 : "=r"(r[0]), "=r"(r[1]), "=r"(r[2]), "=r"(r[3]) : "r"(a));
}
__device__ __forceinline__ void ldsm_x2(uint32_t& r0, uint32_t& r1, uint32_t a) {
    asm volatile("ldmatrix.sync.aligned.m8n8.x2.shared.b16 {%0,%1}, [%2];"
                 : "=r"(r0), "=r"(r1) : "r"(a));
}
__device__ __forceinline__ void mma16816(float* c, const uint32_t* a, const uint32_t* b) {
    asm volatile(
        "mma.sync.aligned.m16n8k16.row.col.f32.f16.f16.f32 "
        "{%0,%1,%2,%3}, {%4,%5,%6,%7}, {%8,%9}, {%0,%1,%2,%3};"
        : "+f"(c[0]), "+f"(c[1]), "+f"(c[2]), "+f"(c[3])
        : "r"(a[0]), "r"(a[1]), "r"(a[2]), "r"(a[3]), "r"(b[0]), "r"(b[1]));
}

// ===========================================================================
// conversions
// ===========================================================================
__global__ __launch_bounds__(256) void convert_W_kernel(
    const float* __restrict__ Wth, const float* __restrict__ Wph)
{
    int i = blockIdx.x * 256 + threadIdx.x;
    float w = (i < CI * CDIM) ? Wth[i] : Wph[i - CI * CDIM];
    g_Wh[i] = __float2half(w);
    if (i < BATCH * NPOS) g_abar[i] = 0.f;
    if (i < BATCH * CDIM) { g_xw[i] = 0.f; g_xbar[i] = 0.f; }
}

// X [b][c][n] fp32 -> X^T [b][n][c] fp16; 64x64 tiles, vectorized IO
#define CX_PITCH 72
__global__ __launch_bounds__(256) void convert_X_kernel(const float* __restrict__ x)
{
    __shared__ __half tile[64 * CX_PITCH];
    const int b   = blockIdx.z;
    const int c0  = blockIdx.y * 64;
    const int n0  = blockIdx.x * 64;
    const int tid = threadIdx.x;

    #pragma unroll
    for (int i = 0; i < 4; i++) {
        int t = tid + i * 256;
        int c = t >> 4, nq = t & 15;
        int n = n0 + nq * 4;
        float4 v = make_float4(0.f, 0.f, 0.f, 0.f);
        if (n < NPOS)
            v = *reinterpret_cast<const float4*>(
                x + ((size_t)b * CDIM + c0 + c) * NPOS + n);
        __half2 h01 = __floats2half2_rn(v.x, v.y);
        __half2 h23 = __floats2half2_rn(v.z, v.w);
        uint2 pk;
        pk.x = *reinterpret_cast<uint32_t*>(&h01);
        pk.y = *reinterpret_cast<uint32_t*>(&h23);
        *reinterpret_cast<uint2*>(tile + c * CX_PITCH + nq * 4) = pk;
    }
    __syncthreads();
    #pragma unroll
    for (int i = 0; i < 2; i++) {
        int t = tid + i * 256;
        int n = t >> 3, cq = t & 7;
        if (n0 + n < NPOS) {
            __align__(16) __half h8[8];
            #pragma unroll
            for (int k = 0; k < 8; k++)
                h8[k] = tile[(cq * 8 + k) * CX_PITCH + n];
            *reinterpret_cast<uint4*>(
                g_Xt + ((size_t)b * NPOS + n0 + n) * CDIM + c0 + cq * 8) =
                *reinterpret_cast<const uint4*>(h8);
        }
    }
}

// ===========================================================================
// GEMM1 (warp MMA, fp16): C[m][n] = sum_k W[m][k] X^T[n][k]
// CTA tile 128x112, 4 warps (2M x 2N), warp tile 64x56.
// 3-stage cp.async pipeline (K=32 stages).
// ===========================================================================
#define G1_BOFF  10240           // A: 128 rows * 80B
#define G1_STAGE 19200           // + B: 112 rows * 80B
#define G1_SMEM  57600
#define G1_EPITCH 144            // halves per n-row in epilogue bounce

__global__ __launch_bounds__(128, 3) void gemm1_mma(
    const float* __restrict__ bth, const float* __restrict__ bph)
{
    extern __shared__ char smc[];
    const uint32_t sbase = smem_u32(smc);
    const int tid  = threadIdx.x;
    const int lane = tid & 31;
    const int wid  = tid >> 5;           // 0..3
    const int wm   = wid >> 1;           // 0..1  (M, 64 rows)
    const int wn   = wid & 1;            // 0..1  (N, 56 cols)
    const int b    = blockIdx.z;
    const int m0   = blockIdx.y * 128;
    const int n0   = blockIdx.x * 112;

    float acc[28][4];
    #pragma unroll
    for (int i = 0; i < 28; i++)
        #pragma unroll
        for (int j = 0; j < 4; j++) acc[i][j] = 0.f;

    auto issue = [&](int kt, int buf) {
        const int k0 = kt * 32;
        const uint32_t st = sbase + buf * G1_STAGE;
        #pragma unroll
        for (int i = 0; i < 4; i++) {           // A: 512 tasks
            int t = tid + i * 128;
            int row = t >> 2, ch = t & 3;
            const __half* src = g_Wh + (size_t)(m0 + row) * CDIM + k0 + ch * 8;
            cp16(st + row * 80 + ch * 16, src);
        }
        #pragma unroll
        for (int i = 0; i < 4; i++) {           // B: 448 tasks
            int t = tid + i * 128;
            if (t < 448) {
                int row = t >> 2, ch = t & 3;
                const __half* src = g_Xt
                    + ((size_t)b * NPOS + n0 + row) * CDIM + k0 + ch * 8;
                cp16(st + G1_BOFF + row * 80 + ch * 16, src);
            }
        }
        CP_COMMIT();
    };

    issue(0, 0);
    issue(1, 1);
    issue(2, 2);

    const int arow = lane & 15;
    const int ach  = lane >> 4;
    const int brow = ((lane >> 4) << 3) + (lane & 7);
    const int bch  = (lane >> 3) & 1;
    const int brow2 = (lane & 15) & 7;
    const int bch2  = ((lane & 15) >> 3) & 1;

    int buf = 0, pbuf = 0;
    for (int kt = 0; kt < 32; kt++) {
        CP_WAIT_2();
        __syncthreads();
        const uint32_t st = sbase + buf * G1_STAGE;
        #pragma unroll
        for (int s = 0; s < 2; s++) {
            uint32_t ah[4][4], bb[7][2];
            #pragma unroll
            for (int p = 0; p < 3; p++) {
                uint32_t ba = st + G1_BOFF + (wn * 56 + p * 16 + brow) * 80 + (s * 2 + bch) * 16;
                uint32_t r[4]; ldsm_x4(r, ba);
                bb[p*2][0] = r[0]; bb[p*2][1] = r[1];
                bb[p*2+1][0] = r[2]; bb[p*2+1][1] = r[3];
            }
            ldsm_x2(bb[6][0], bb[6][1],
                    st + G1_BOFF + (wn * 56 + 48 + brow2) * 80 + (s * 2 + bch2) * 16);
            #pragma unroll
            for (int i = 0; i < 4; i++) {
                uint32_t aa = st + (wm * 64 + i * 16 + arow) * 80 + (s * 2 + ach) * 16;
                ldsm_x4(ah[i], aa);
            }
            #pragma unroll
            for (int i = 0; i < 4; i++)
                #pragma unroll
                for (int j = 0; j < 7; j++)
                    mma16816(acc[i*7+j], ah[i], bb[j]);
        }
        __syncthreads();
        if (kt + 3 < 32) issue(kt + 3, pbuf); else CP_COMMIT();
        buf  = (buf == 2)  ? 0 : buf + 1;
        pbuf = (pbuf == 2) ? 0 : pbuf + 1;
    }

    // ---- epilogue: fp16 bounce [n][ch] pitch 144, then uint4 biased stores
    __syncthreads();
    __half* eb = reinterpret_cast<__half*>(smc);
    #pragma unroll
    for (int i = 0; i < 4; i++)
        #pragma unroll
        for (int j = 0; j < 7; j++) {
            int ch  = wm * 64 + i * 16 + (lane >> 2);
            int col = wn * 56 + j * 8 + (lane & 3) * 2;
            eb[col * G1_EPITCH + ch]           = __float2half(acc[i*7+j][0]);
            eb[(col + 1) * G1_EPITCH + ch]     = __float2half(acc[i*7+j][1]);
            eb[col * G1_EPITCH + ch + 8]       = __float2half(acc[i*7+j][2]);
            eb[(col + 1) * G1_EPITCH + ch + 8] = __float2half(acc[i*7+j][3]);
        }
    __syncthreads();

    const bool isTheta = (m0 < CI);
    __half* dst = isTheta ? g_Th : g_Ph;
    const int ch0g = isTheta ? m0 : (m0 - CI);
    const float* bias = isTheta ? bth : bph;

    #pragma unroll
    for (int it = 0; it < 14; it++) {
        int t  = tid + it * 128;       // 0..1791
        int cg = t & 15, n = t >> 4;
        int chl = cg * 8;
        uint4 raw = *reinterpret_cast<const uint4*>(eb + n * G1_EPITCH + chl);
        const __half* rh = reinterpret_cast<const __half*>(&raw);
        __align__(16) __half h8[8];
        #pragma unroll
        for (int k = 0; k < 8; k++)
            h8[k] = __float2half(__half2float(rh[k]) + bias[ch0g + chl + k]);
        size_t off = ((size_t)b * NPOS + n0 + n) * CI + ch0g + chl;
        *reinterpret_cast<uint4*>(dst + off) = *reinterpret_cast<const uint4*>(h8);
    }
}

// ===========================================================================
// GEMM2 (warp MMA, fp16): F[n][m] = sum_k Th[n][k] Ph[m][k]
// CTA tile 128(n, clamped) x 112(m), 8 warps (4M x 2N), warp 32x56.
// K=64 stages, 2-stage pipeline (pitch 144B).
// Epilogue: register-resident row stats, exp in regs, fp16 E bounce.
// ===========================================================================
#define G2_PITCH 144
#define G2_BOFF  18432           // A: 128 rows * 144B
#define G2_STAGE 34560           // + B: 112 rows * 144B
#define G2_SMEM  69120
#define G2_EPH   120             // halves per row in fp16 E bounce

__global__ __launch_bounds__(256, 2) void gemm2_mma()
{
    extern __shared__ char smc[];
    const uint32_t sbase = smem_u32(smc);
    const int tid  = threadIdx.x;
    const int lane = tid & 31;
    const int wid  = tid >> 5;           // 0..7
    const int wm   = wid >> 1;           // 0..3  (rows n, 32 each)
    const int wn   = wid & 1;            // 0..1  (cols m, 56 each)
    const int b    = blockIdx.z;
    const int n0   = blockIdx.y * 128;   // rows (theta), padded range
    const int cbx  = blockIdx.x;         // col block 0..6
    const int mb0  = cbx * 112;          // cols (phi)

    float acc[14][4];
    #pragma unroll
    for (int i = 0; i < 14; i++)
        #pragma unroll
        for (int j = 0; j < 4; j++) acc[i][j] = 0.f;

    auto issue = [&](int kt, int buf) {
        const int k0 = kt * 64;
        const uint32_t st = sbase + buf * G2_STAGE;
        #pragma unroll
        for (int i = 0; i < 4; i++) {    // A: 1024 tasks, clamp row
            int t = tid + i * 256;
            int row = t >> 3, ch = t & 7;
            int gn = n0 + row; if (gn > NPOS - 1) gn = NPOS - 1;
            const __half* asrc = g_Th
                + ((size_t)b * NPOS + gn) * CI + k0 + ch * 8;
            cp16(st + row * G2_PITCH + ch * 16, asrc);
        }
        #pragma unroll
        for (int i = 0; i < 4; i++) {    // B: 896 tasks
            int t = tid + i * 256;
            if (t < 896) {
                int row = t >> 3, ch = t & 7;
                const __half* bsrc = g_Ph
                    + ((size_t)b * NPOS + mb0 + row) * CI + k0 + ch * 8;
                cp16(st + G2_BOFF + row * G2_PITCH + ch * 16, bsrc);
            }
        }
        CP_COMMIT();
    };

    issue(0, 0);
    issue(1, 1);

    const int arow = lane & 15;
    const int ach  = lane >> 4;
    const int brow = ((lane >> 4) << 3) + (lane & 7);
    const int bch  = (lane >> 3) & 1;
    const int brow2 = (lane & 15) & 7;
    const int bch2  = ((lane & 15) >> 3) & 1;

    int buf = 0;
    for (int kt = 0; kt < 8; kt++) {
        CP_WAIT_1();
        __syncthreads();
        const uint32_t st = sbase + buf * G2_STAGE;
        #pragma unroll
        for (int s = 0; s < 4; s++) {
            uint32_t ah[2][4], bb[7][2];
            #pragma unroll
            for (int i = 0; i < 2; i++) {
                uint32_t aa = st + (wm * 32 + i * 16 + arow) * G2_PITCH + (s * 2 + ach) * 16;
                ldsm_x4(ah[i], aa);
            }
            #pragma unroll
            for (int p = 0; p < 3; p++) {
                uint32_t ba = st + G2_BOFF + (wn * 56 + p * 16 + brow) * G2_PITCH + (s * 2 + bch) * 16;
                uint32_t r[4]; ldsm_x4(r, ba);
                bb[p*2][0] = r[0]; bb[p*2][1] = r[1];
                bb[p*2+1][0] = r[2]; bb[p*2+1][1] = r[3];
            }
            ldsm_x2(bb[6][0], bb[6][1],
                    st + G2_BOFF + (wn * 56 + 48 + brow2) * G2_PITCH + (s * 2 + bch2) * 16);
            #pragma unroll
            for (int i = 0; i < 2; i++)
                #pragma unroll
                for (int j = 0; j < 7; j++)
                    mma16816(acc[i*7+j], ah[i], bb[j]);
        }
        __syncthreads();
        if (kt + 2 < 8) issue(kt + 2, buf); else CP_COMMIT();
        buf ^= 1;
    }

    // ======== epilogue: register-resident stats + fp16 E bounce ========
    __syncthreads();
    __half* ebh  = reinterpret_cast<__half*>(smc);                 // [128][120] halves
    float* rmax2 = reinterpret_cast<float*>(smc + 30720);          // [128][2]
    float* psum2 = reinterpret_cast<float*>(smc + 30720 + 1024);   // [128][2]

    const int r = lane >> 2;   // 0..7
    const int q = lane & 3;    // 0..3

    float rmx[4];
    #pragma unroll
    for (int i = 0; i < 2; i++) {
        float m0 = -CUDART_INF_F, m1 = -CUDART_INF_F;
        #pragma unroll
        for (int j = 0; j < 7; j++) {
            m0 = fmaxf(m0, fmaxf(acc[i*7+j][0], acc[i*7+j][1]));
            m1 = fmaxf(m1, fmaxf(acc[i*7+j][2], acc[i*7+j][3]));
        }
        #pragma unroll
        for (int o = 1; o < 4; o <<= 1) {
            m0 = fmaxf(m0, __shfl_xor_sync(0xffffffffu, m0, o));
            m1 = fmaxf(m1, __shfl_xor_sync(0xffffffffu, m1, o));
        }
        rmx[i*2]   = m0;
        rmx[i*2+1] = m1;
    }
    if (q == 0) {
        #pragma unroll
        for (int k = 0; k < 4; k++) {
            int row = wm * 32 + (k >> 1) * 16 + (k & 1) * 8 + r;
            rmax2[row * 2 + wn] = rmx[k];
        }
    }
    __syncthreads();

    float frmx[4];
    #pragma unroll
    for (int k = 0; k < 4; k++) {
        int row = wm * 32 + (k >> 1) * 16 + (k & 1) * 8 + r;
        frmx[k] = fmaxf(rmax2[row * 2], rmax2[row * 2 + 1]);
    }

    float ps[4] = {0.f, 0.f, 0.f, 0.f};
    #pragma unroll
    for (int i = 0; i < 2; i++) {
        #pragma unroll
        for (int j = 0; j < 7; j++) {
            int col  = wn * 56 + j * 8 + q * 2;
            int row0 = wm * 32 + i * 16 + r;
            float e0 = __expf(acc[i*7+j][0] - frmx[i*2]);
            float e1 = __expf(acc[i*7+j][1] - frmx[i*2]);
            float e2 = __expf(acc[i*7+j][2] - frmx[i*2+1]);
            float e3 = __expf(acc[i*7+j][3] - frmx[i*2+1]);
            ps[i*2]   += e0 + e1;
            ps[i*2+1] += e2 + e3;
            __half2 h01 = __floats2half2_rn(e0, e1);
            __half2 h23 = __floats2half2_rn(e2, e3);
            *reinterpret_cast<__half2*>(ebh + row0 * G2_EPH + col)       = h01;
            *reinterpret_cast<__half2*>(ebh + (row0 + 8) * G2_EPH + col) = h23;
        }
    }
    #pragma unroll
    for (int k = 0; k < 4; k++)
        #pragma unroll
        for (int o = 1; o < 4; o <<= 1)
            ps[k] += __shfl_xor_sync(0xffffffffu, ps[k], o);
    if (q == 0) {
        #pragma unroll
        for (int k = 0; k < 4; k++) {
            int row = wm * 32 + (k >> 1) * 16 + (k & 1) * 8 + r;
            psum2[row * 2 + wn] = ps[k];
        }
    }
    __syncthreads();

    if (tid < 128 && n0 + tid < NPOS) {
        int o = (b * 7 + cbx) * NPOS + n0 + tid;
        g_pmax[o] = fmaxf(rmax2[tid * 2], rmax2[tid * 2 + 1]);
        g_psum[o] = psum2[tid * 2] + psum2[tid * 2 + 1];
    }

    #pragma unroll
    for (int i = 0; i < 7; i++) {
        int t = tid + i * 256;          // 0..1791
        int row = t / 14, cg = t % 14;
        if (n0 + row < NPOS) {
            uint4 v = *reinterpret_cast<const uint4*>(ebh + row * G2_EPH + cg * 8);
            *reinterpret_cast<uint4*>(
                g_E + ((size_t)b * NPOS + n0 + row) * NPOS + mb0 + cg * 8) = v;
        }
    }
}

// ===========================================================================
// colsum (vectorized, inline combine):
// a_bar[b][m] += sum_n E[n][m] * w[n][cb(m)]; thread handles 4 adjacent m.
// grid (1, 14 n-chunks of 56, BATCH), block 196.
// ===========================================================================
__global__ __launch_bounds__(196) void colsum_kernel()
{
    const int b  = blockIdx.z;
    const int n0 = blockIdx.y * 56;
    const int t  = threadIdx.x;          // 0..195
    const int m4 = t * 4;                // 0..780
    const int cbx = m4 / 112;            // 0..6

    __shared__ float sw[7][56];
    if (t < 56) {
        int n = n0 + t;
        float pm[7];
        float mx = -CUDART_INF_F;
        #pragma unroll
        for (int cb = 0; cb < 7; cb++) {
            pm[cb] = g_pmax[(b * 7 + cb) * NPOS + n];
            mx = fmaxf(mx, pm[cb]);
        }
        float s = 0.f;
        #pragma unroll
        for (int cb = 0; cb < 7; cb++)
            s += g_psum[(b * 7 + cb) * NPOS + n] * __expf(pm[cb] - mx);
        float inv = 1.f / (s * (float)NPOS);
        #pragma unroll
        for (int cb = 0; cb < 7; cb++)
            sw[cb][t] = __expf(pm[cb] - mx) * inv;
    }
    __syncthreads();

    const __half* __restrict__ Eb = g_E + ((size_t)b * NPOS + n0) * NPOS + m4;
    float a0 = 0.f, a1 = 0.f, a2 = 0.f, a3 = 0.f;
    #pragma unroll 8
    for (int j = 0; j < 56; j++) {
        uint2 v = *reinterpret_cast<const uint2*>(Eb + (size_t)j * NPOS);
        __half2 h01 = *reinterpret_cast<__half2*>(&v.x);
        __half2 h23 = *reinterpret_cast<__half2*>(&v.y);
        float2 f01 = __half22float2(h01);
        float2 f23 = __half22float2(h23);
        float w = sw[cbx][j];
        a0 = fmaf(f01.x, w, a0);
        a1 = fmaf(f01.y, w, a1);
        a2 = fmaf(f23.x, w, a2);
        a3 = fmaf(f23.y, w, a3);
    }
    atomicAdd(&g_abar[b * NPOS + m4 + 0], a0);
    atomicAdd(&g_abar[b * NPOS + m4 + 1], a1);
    atomicAdd(&g_abar[b * NPOS + m4 + 2], a2);
    atomicAdd(&g_abar[b * NPOS + m4 + 3], a3);
}

// xw[b][c] += sum_n Xt[b][n][c]*abar[n];  xbar[b][c] += sum_n Xt[b][n][c]/784
__global__ __launch_bounds__(256) void xw_kernel()
{
    const int b   = blockIdx.z;
    const int c0  = blockIdx.x * 512;
    const int n0  = blockIdx.y * 98;
    const int tid = threadIdx.x;

    __shared__ float sa[98];
    if (tid < 98) sa[tid] = g_abar[b * NPOS + n0 + tid];
    __syncthreads();

    const __half2* __restrict__ Xt2 = reinterpret_cast<const __half2*>(
        g_Xt + ((size_t)b * NPOS + n0) * CDIM + c0) + tid;

    float d0 = 0.f, d1 = 0.f, s0 = 0.f, s1 = 0.f;
    #pragma unroll 7
    for (int n = 0; n < 98; n++) {
        __half2 h = Xt2[(size_t)n * (CDIM / 2)];
        float2 f = __half22float2(h);
        float a = sa[n];
        d0 = fmaf(f.x, a, d0);
        d1 = fmaf(f.y, a, d1);
        s0 += f.x;
        s1 += f.y;
    }
    int c = c0 + tid * 2;
    atomicAdd(&g_xw[b * CDIM + c],       d0);
    atomicAdd(&g_xw[b * CDIM + c + 1],   d1);
    atomicAdd(&g_xbar[b * CDIM + c],     s0 * (1.f / (float)NPOS));
    atomicAdd(&g_xbar[b * CDIM + c + 1], s1 * (1.f / (float)NPOS));
}

__global__ __launch_bounds__(256) void ybar_kernel(const float* __restrict__ Wg,
                                                   const float* __restrict__ bg)
{
    const int b    = blockIdx.y;
    const int i    = blockIdx.x * 8 + (threadIdx.x >> 5);
    const int lane = threadIdx.x & 31;

    __shared__ float sx[CDIM];
    for (int k = threadIdx.x; k < CDIM; k += 256) sx[k] = g_xw[b * CDIM + k];
    __syncthreads();

    const float* __restrict__ w = Wg + (size_t)i * CDIM;
    float d = 0.f;
    for (int k = lane; k < CDIM; k += 32) d = fmaf(w[k], sx[k], d);
    #pragma unroll
    for (int o = 16; o; o >>= 1) d += __shfl_xor_sync(0xffffffffu, d, o);
    if (lane == 0) g_ybar[b * CI + i] = d + bg[i];
}

__global__ __launch_bounds__(256) void pooled_kernel(
    const float* __restrict__ Ww, const float* __restrict__ bw,
    const float* __restrict__ gamma, const float* __restrict__ beta,
    const float* __restrict__ bmean, const float* __restrict__ bvar)
{
    const int b    = blockIdx.y;
    const int c    = blockIdx.x * 8 + (threadIdx.x >> 5);
    const int lane = threadIdx.x & 31;

    __shared__ float sy[CI];
    for (int k = threadIdx.x; k < CI; k += 256) sy[k] = g_ybar[b * CI + k];
    __syncthreads();

    const float* __restrict__ w = Ww + (size_t)c * CI;
    float d = 0.f;
    for (int k = lane; k < CI; k += 32) d = fmaf(w[k], sy[k], d);
    #pragma unroll
    for (int o = 16; o; o >>= 1) d += __shfl_xor_sync(0xffffffffu, d, o);
    if (lane == 0) {
        float inv = gamma[c] * rsqrtf(bvar[c] + 1e-5f);
        g_pooled[b * CDIM + c] =
            inv * (d + bw[c]) + (beta[c] - bmean[c] * inv) + g_xbar[b * CDIM + c];
    }
}

__global__ __launch_bounds__(256) void h_kernel(const float* __restrict__ W1,
                                                const float* __restrict__ b1)
{
    const int b    = blockIdx.y;
    const int j    = blockIdx.x * 8 + (threadIdx.x >> 5);
    const int lane = threadIdx.x & 31;

    __shared__ float sp[CDIM];
    for (int k = threadIdx.x; k < CDIM; k += 256) sp[k] = g_pooled[b * CDIM + k];
    __syncthreads();

    const float* __restrict__ w = W1 + (size_t)j * CDIM;
    float d = 0.f;
    for (int k = lane; k < CDIM; k += 32) d = fmaf(w[k], sp[k], d);
    #pragma unroll
    for (int o = 16; o; o >>= 1) d += __shfl_xor_sync(0xffffffffu, d, o);
    if (lane == 0) g_h[b * CI + j] = d + b1[j];
}

__global__ __launch_bounds__(256) void out_kernel(const float* __restrict__ xface,
                                                  const float* __restrict__ W2,
                                                  const float* __restrict__ b2,
                                                  float* __restrict__ out)
{
    const int b = blockIdx.x;
    const int o = threadIdx.x >> 7;
    const int t = threadIdx.x & 127;

    float acc = 0.f;
    for (int k = t; k < CDIM; k += 128) {
        float v = (k < CI) ? g_h[b * CI + k] : xface[b * CI + (k - CI)];
        acc = fmaf(W2[o * CDIM + k], v, acc);
    }
    #pragma unroll
    for (int off = 16; off; off >>= 1) acc += __shfl_xor_sync(0xffffffffu, acc, off);

    __shared__ float sred[8];
    const int warp = threadIdx.x >> 5;
    if ((threadIdx.x & 31) == 0) sred[warp] = acc;
    __syncthreads();
    if (threadIdx.x == 0)
        out[b * 2 + 0] = sred[0] + sred[1] + sred[2] + sred[3] + b2[0];
    if (threadIdx.x == 128)
        out[b * 2 + 1] = sred[4] + sred[5] + sred[6] + sred[7] + b2[1];
}

// ===========================================================================
extern "C" void kernel_launch(void* const* d_in, const int* in_sizes, int n_in,
                              void* d_out, int out_size)
{
    const float* x_body = (const float*)d_in[0];
    const float* x_face = (const float*)d_in[1];
    const float* Wg     = (const float*)d_in[2];
    const float* bg     = (const float*)d_in[3];
    const float* Wth    = (const float*)d_in[4];
    const float* bth    = (const float*)d_in[5];
    const float* Wph    = (const float*)d_in[6];
    const float* bph    = (const float*)d_in[7];
    const float* Ww     = (const float*)d_in[8];
    const float* bw     = (const float*)d_in[9];
    const float* gamma  = (const float*)d_in[10];
    const float* beta   = (const float*)d_in[11];
    const float* bmean  = (const float*)d_in[12];
    const float* bvar   = (const float*)d_in[13];
    const float* W1     = (const float*)d_in[14];
    const float* b1     = (const float*)d_in[15];
    const float* W2     = (const float*)d_in[16];
    const float* b2     = (const float*)d_in[17];
    float* out = (float*)d_out;

    cudaFuncSetAttribute(gemm1_mma, cudaFuncAttributeMaxDynamicSharedMemorySize, G1_SMEM);
    cudaFuncSetAttribute(gemm2_mma, cudaFuncAttributeMaxDynamicSharedMemorySize, G2_SMEM);

    convert_W_kernel<<<(CDIM * CDIM) / 256, 256>>>(Wth, Wph);
    convert_X_kernel<<<dim3((NPOS + 63) / 64, CDIM / 64, BATCH), 256>>>(x_body);

    gemm1_mma<<<dim3(NPOS / 112, CDIM / 128, BATCH), 128, G1_SMEM>>>(bth, bph);
    gemm2_mma<<<dim3(NPOS / 112, (NPOS + 127) / 128, BATCH), 256, G2_SMEM>>>();

    colsum_kernel<<<dim3(1, 14, BATCH), 196>>>();
    xw_kernel<<<dim3(2, 8, BATCH), 256>>>();
    ybar_kernel<<<dim3(CI / 8, BATCH), 256>>>(Wg, bg);
    pooled_kernel<<<dim3(CDIM / 8, BATCH), 256>>>(Ww, bw, gamma, beta, bmean, bvar);
    h_kernel<<<dim3(CI / 8, BATCH), 256>>>(W1, b1);
    out_kernel<<<BATCH, 256>>>(x_face, W2, b2, out);
}

// round 16
// speedup vs baseline: 2.1285x; 1.0537x over previous
#include <cuda_runtime.h>
#include <cuda_fp16.h>
#include <math_constants.h>
#include <cstdint>

#define BATCH 32
#define CDIM  1024
#define CI    512
#define NPOS  784

// -------- scratch (device globals) --------
__device__ __align__(16) __half g_Wh[(size_t)CDIM * CDIM];          // W fp16 (theta rows 0..511, phi 512..1023)
__device__ __align__(16) __half g_Xt[(size_t)BATCH * NPOS * CDIM];  // X^T fp16 [b][n][c]
__device__ __align__(16) __half g_Th[(size_t)BATCH * NPOS * CI];    // theta^T fp16 [b][n][k]
__device__ __align__(16) __half g_Ph[(size_t)BATCH * NPOS * CI];    // phi^T fp16
__device__ __align__(16) __half g_E[(size_t)BATCH * NPOS * NPOS];   // exp(f - pmax[row,cb]) fp16
__device__ float g_pmax[BATCH * 7 * NPOS];   // per-colblock row max
__device__ float g_psum[BATCH * 7 * NPOS];   // per-colblock row sumexp
__device__ float g_abar[BATCH * NPOS];
__device__ float g_xw[BATCH * CDIM];
__device__ float g_xbar[BATCH * CDIM];
__device__ float g_ybar[BATCH * CI];
__device__ float g_pooled[BATCH * CDIM];
__device__ float g_h[BATCH * CI];

// -------- helpers --------
__device__ __forceinline__ uint32_t smem_u32(const void* p) {
    uint32_t a;
    asm("{ .reg .u64 t; cvta.to.shared.u64 t, %1; cvt.u32.u64 %0, t; }" : "=r"(a) : "l"(p));
    return a;
}
__device__ __forceinline__ void cp16(uint32_t dst, const void* src) {
    asm volatile("cp.async.cg.shared.global [%0], [%1], 16;" :: "r"(dst), "l"(src) : "memory");
}
#define CP_COMMIT() asm volatile("cp.async.commit_group;" ::: "memory")
#define CP_WAIT_1() asm volatile("cp.async.wait_group 1;" ::: "memory")

__device__ __forceinline__ void ldsm_x4(uint32_t (&r)[4], uint32_t a) {
    asm volatile("ldmatrix.sync.aligned.m8n8.x4.shared.b16 {%0,%1,%2,%3}, [%4];"
                 : "=r"(r[0]), "=r"(r[1]), "=r"(r[2]), "=r"(r[3]) : "r"(a));
}
__device__ __forceinline__ void ldsm_x2(uint32_t& r0, uint32_t& r1, uint32_t a) {
    asm volatile("ldmatrix.sync.aligned.m8n8.x2.shared.b16 {%0,%1}, [%2];"
                 : "=r"(r0), "=r"(r1) : "r"(a));
}
__device__ __forceinline__ void mma16816(float* c, const uint32_t* a, const uint32_t* b) {
    asm volatile(
        "mma.sync.aligned.m16n8k16.row.col.f32.f16.f16.f32 "
        "{%0,%1,%2,%3}, {%4,%5,%6,%7}, {%8,%9}, {%0,%1,%2,%3};"
        : "+f"(c[0]), "+f"(c[1]), "+f"(c[2]), "+f"(c[3])
        : "r"(a[0]), "r"(a[1]), "r"(a[2]), "r"(a[3]), "r"(b[0]), "r"(b[1]));
}

// ===========================================================================
// conversions
// ===========================================================================
__global__ __launch_bounds__(256) void convert_W_kernel(
    const float* __restrict__ Wth, const float* __restrict__ Wph)
{
    int i = blockIdx.x * 256 + threadIdx.x;
    float w = (i < CI * CDIM) ? Wth[i] : Wph[i - CI * CDIM];
    g_Wh[i] = __float2half(w);
    if (i < BATCH * NPOS) g_abar[i] = 0.f;
    if (i < BATCH * CDIM) { g_xw[i] = 0.f; g_xbar[i] = 0.f; }
}

// X [b][c][n] fp32 -> X^T [b][n][c] fp16; 64x64 tiles, vectorized IO
#define CX_PITCH 72
__global__ __launch_bounds__(256) void convert_X_kernel(const float* __restrict__ x)
{
    __shared__ __half tile[64 * CX_PITCH];
    const int b   = blockIdx.z;
    const int c0  = blockIdx.y * 64;
    const int n0  = blockIdx.x * 64;
    const int tid = threadIdx.x;

    #pragma unroll
    for (int i = 0; i < 4; i++) {
        int t = tid + i * 256;
        int c = t >> 4, nq = t & 15;
        int n = n0 + nq * 4;
        float4 v = make_float4(0.f, 0.f, 0.f, 0.f);
        if (n < NPOS)
            v = *reinterpret_cast<const float4*>(
                x + ((size_t)b * CDIM + c0 + c) * NPOS + n);
        __half2 h01 = __floats2half2_rn(v.x, v.y);
        __half2 h23 = __floats2half2_rn(v.z, v.w);
        uint2 pk;
        pk.x = *reinterpret_cast<uint32_t*>(&h01);
        pk.y = *reinterpret_cast<uint32_t*>(&h23);
        *reinterpret_cast<uint2*>(tile + c * CX_PITCH + nq * 4) = pk;
    }
    __syncthreads();
    #pragma unroll
    for (int i = 0; i < 2; i++) {
        int t = tid + i * 256;
        int n = t >> 3, cq = t & 7;
        if (n0 + n < NPOS) {
            __align__(16) __half h8[8];
            #pragma unroll
            for (int k = 0; k < 8; k++)
                h8[k] = tile[(cq * 8 + k) * CX_PITCH + n];
            *reinterpret_cast<uint4*>(
                g_Xt + ((size_t)b * NPOS + n0 + n) * CDIM + c0 + cq * 8) =
                *reinterpret_cast<const uint4*>(h8);
        }
    }
}

// ===========================================================================
// GEMM1 (warp MMA, fp16): C[m][n] = sum_k W[m][k] X^T[n][k]
// CTA tile 128x112, 4 warps (2M x 2N), warp tile 64x56.
// K=64 stages, 2-stage cp.async pipeline (pitch 144B).
// SMEM: 2*34560 = 69120; 3 CTAs/SM (207KB)
// ===========================================================================
#define G1_PITCH 144
#define G1_BOFF  18432           // A: 128 rows * 144B
#define G1_STAGE 34560           // + B: 112 rows * 144B
#define G1_SMEM  69120
#define G1_EPITCH 144            // halves per n-row in epilogue bounce

__global__ __launch_bounds__(128, 3) void gemm1_mma(
    const float* __restrict__ bth, const float* __restrict__ bph)
{
    extern __shared__ char smc[];
    const uint32_t sbase = smem_u32(smc);
    const int tid  = threadIdx.x;
    const int lane = tid & 31;
    const int wid  = tid >> 5;           // 0..3
    const int wm   = wid >> 1;           // 0..1  (M, 64 rows)
    const int wn   = wid & 1;            // 0..1  (N, 56 cols)
    const int b    = blockIdx.z;
    const int m0   = blockIdx.y * 128;
    const int n0   = blockIdx.x * 112;

    float acc[28][4];
    #pragma unroll
    for (int i = 0; i < 28; i++)
        #pragma unroll
        for (int j = 0; j < 4; j++) acc[i][j] = 0.f;

    auto issue = [&](int kt, int buf) {
        const int k0 = kt * 64;
        const uint32_t st = sbase + buf * G1_STAGE;
        #pragma unroll
        for (int i = 0; i < 8; i++) {           // A: 1024 tasks of 16B
            int t = tid + i * 128;
            int row = t >> 3, ch = t & 7;
            const __half* src = g_Wh + (size_t)(m0 + row) * CDIM + k0 + ch * 8;
            cp16(st + row * G1_PITCH + ch * 16, src);
        }
        #pragma unroll
        for (int i = 0; i < 7; i++) {           // B: 896 tasks
            int t = tid + i * 128;
            int row = t >> 3, ch = t & 7;
            const __half* src = g_Xt
                + ((size_t)b * NPOS + n0 + row) * CDIM + k0 + ch * 8;
            cp16(st + G1_BOFF + row * G1_PITCH + ch * 16, src);
        }
        CP_COMMIT();
    };

    issue(0, 0);
    issue(1, 1);

    const int arow = lane & 15;
    const int ach  = lane >> 4;
    const int brow = ((lane >> 4) << 3) + (lane & 7);
    const int bch  = (lane >> 3) & 1;
    const int brow2 = (lane & 15) & 7;
    const int bch2  = ((lane & 15) >> 3) & 1;

    int buf = 0;
    for (int kt = 0; kt < 16; kt++) {
        CP_WAIT_1();
        __syncthreads();
        const uint32_t st = sbase + buf * G1_STAGE;
        #pragma unroll
        for (int s = 0; s < 4; s++) {
            uint32_t ah[4][4], bb[7][2];
            #pragma unroll
            for (int p = 0; p < 3; p++) {
                uint32_t ba = st + G1_BOFF + (wn * 56 + p * 16 + brow) * G1_PITCH + (s * 2 + bch) * 16;
                uint32_t r[4]; ldsm_x4(r, ba);
                bb[p*2][0] = r[0]; bb[p*2][1] = r[1];
                bb[p*2+1][0] = r[2]; bb[p*2+1][1] = r[3];
            }
            ldsm_x2(bb[6][0], bb[6][1],
                    st + G1_BOFF + (wn * 56 + 48 + brow2) * G1_PITCH + (s * 2 + bch2) * 16);
            #pragma unroll
            for (int i = 0; i < 4; i++) {
                uint32_t aa = st + (wm * 64 + i * 16 + arow) * G1_PITCH + (s * 2 + ach) * 16;
                ldsm_x4(ah[i], aa);
            }
            #pragma unroll
            for (int i = 0; i < 4; i++)
                #pragma unroll
                for (int j = 0; j < 7; j++)
                    mma16816(acc[i*7+j], ah[i], bb[j]);
        }
        __syncthreads();
        if (kt + 2 < 16) issue(kt + 2, buf); else CP_COMMIT();
        buf ^= 1;
    }

    // ---- epilogue: fp16 bounce [n][ch] pitch 144, then uint4 biased stores
    __syncthreads();
    __half* eb = reinterpret_cast<__half*>(smc);
    #pragma unroll
    for (int i = 0; i < 4; i++)
        #pragma unroll
        for (int j = 0; j < 7; j++) {
            int ch  = wm * 64 + i * 16 + (lane >> 2);
            int col = wn * 56 + j * 8 + (lane & 3) * 2;
            eb[col * G1_EPITCH + ch]           = __float2half(acc[i*7+j][0]);
            eb[(col + 1) * G1_EPITCH + ch]     = __float2half(acc[i*7+j][1]);
            eb[col * G1_EPITCH + ch + 8]       = __float2half(acc[i*7+j][2]);
            eb[(col + 1) * G1_EPITCH + ch + 8] = __float2half(acc[i*7+j][3]);
        }
    __syncthreads();

    const bool isTheta = (m0 < CI);
    __half* dst = isTheta ? g_Th : g_Ph;
    const int ch0g = isTheta ? m0 : (m0 - CI);
    const float* bias = isTheta ? bth : bph;

    #pragma unroll
    for (int it = 0; it < 14; it++) {
        int t  = tid + it * 128;       // 0..1791
        int cg = t & 15, n = t >> 4;
        int chl = cg * 8;
        uint4 raw = *reinterpret_cast<const uint4*>(eb + n * G1_EPITCH + chl);
        const __half* rh = reinterpret_cast<const __half*>(&raw);
        __align__(16) __half h8[8];
        #pragma unroll
        for (int k = 0; k < 8; k++)
            h8[k] = __float2half(__half2float(rh[k]) + bias[ch0g + chl + k]);
        size_t off = ((size_t)b * NPOS + n0 + n) * CI + ch0g + chl;
        *reinterpret_cast<uint4*>(dst + off) = *reinterpret_cast<const uint4*>(h8);
    }
}

// ===========================================================================
// GEMM2 (warp MMA, fp16): F[n][m] = sum_k Th[n][k] Ph[m][k]
// CTA tile 128(n, clamped) x 112(m), 8 warps (4M x 2N), warp 32x56.
// K=64 stages, 2-stage pipeline (pitch 144B).
// Epilogue: register-resident row stats, exp in regs, fp16 E bounce.
// ===========================================================================
#define G2_PITCH 144
#define G2_BOFF  18432           // A: 128 rows * 144B
#define G2_STAGE 34560           // + B: 112 rows * 144B
#define G2_SMEM  69120
#define G2_EPH   120             // halves per row in fp16 E bounce

__global__ __launch_bounds__(256, 2) void gemm2_mma()
{
    extern __shared__ char smc[];
    const uint32_t sbase = smem_u32(smc);
    const int tid  = threadIdx.x;
    const int lane = tid & 31;
    const int wid  = tid >> 5;           // 0..7
    const int wm   = wid >> 1;           // 0..3  (rows n, 32 each)
    const int wn   = wid & 1;            // 0..1  (cols m, 56 each)
    const int b    = blockIdx.z;
    const int n0   = blockIdx.y * 128;   // rows (theta), padded range
    const int cbx  = blockIdx.x;         // col block 0..6
    const int mb0  = cbx * 112;          // cols (phi)

    float acc[14][4];
    #pragma unroll
    for (int i = 0; i < 14; i++)
        #pragma unroll
        for (int j = 0; j < 4; j++) acc[i][j] = 0.f;

    auto issue = [&](int kt, int buf) {
        const int k0 = kt * 64;
        const uint32_t st = sbase + buf * G2_STAGE;
        #pragma unroll
        for (int i = 0; i < 4; i++) {    // A: 1024 tasks, clamp row
            int t = tid + i * 256;
            int row = t >> 3, ch = t & 7;
            int gn = n0 + row; if (gn > NPOS - 1) gn = NPOS - 1;
            const __half* asrc = g_Th
                + ((size_t)b * NPOS + gn) * CI + k0 + ch * 8;
            cp16(st + row * G2_PITCH + ch * 16, asrc);
        }
        #pragma unroll
        for (int i = 0; i < 4; i++) {    // B: 896 tasks
            int t = tid + i * 256;
            if (t < 896) {
                int row = t >> 3, ch = t & 7;
                const __half* bsrc = g_Ph
                    + ((size_t)b * NPOS + mb0 + row) * CI + k0 + ch * 8;
                cp16(st + G2_BOFF + row * G2_PITCH + ch * 16, bsrc);
            }
        }
        CP_COMMIT();
    };

    issue(0, 0);
    issue(1, 1);

    const int arow = lane & 15;
    const int ach  = lane >> 4;
    const int brow = ((lane >> 4) << 3) + (lane & 7);
    const int bch  = (lane >> 3) & 1;
    const int brow2 = (lane & 15) & 7;
    const int bch2  = ((lane & 15) >> 3) & 1;

    int buf = 0;
    for (int kt = 0; kt < 8; kt++) {
        CP_WAIT_1();
        __syncthreads();
        const uint32_t st = sbase + buf * G2_STAGE;
        #pragma unroll
        for (int s = 0; s < 4; s++) {
            uint32_t ah[2][4], bb[7][2];
            #pragma unroll
            for (int i = 0; i < 2; i++) {
                uint32_t aa = st + (wm * 32 + i * 16 + arow) * G2_PITCH + (s * 2 + ach) * 16;
                ldsm_x4(ah[i], aa);
            }
            #pragma unroll
            for (int p = 0; p < 3; p++) {
                uint32_t ba = st + G2_BOFF + (wn * 56 + p * 16 + brow) * G2_PITCH + (s * 2 + bch) * 16;
                uint32_t r[4]; ldsm_x4(r, ba);
                bb[p*2][0] = r[0]; bb[p*2][1] = r[1];
                bb[p*2+1][0] = r[2]; bb[p*2+1][1] = r[3];
            }
            ldsm_x2(bb[6][0], bb[6][1],
                    st + G2_BOFF + (wn * 56 + 48 + brow2) * G2_PITCH + (s * 2 + bch2) * 16);
            #pragma unroll
            for (int i = 0; i < 2; i++)
                #pragma unroll
                for (int j = 0; j < 7; j++)
                    mma16816(acc[i*7+j], ah[i], bb[j]);
        }
        __syncthreads();
        if (kt + 2 < 8) issue(kt + 2, buf); else CP_COMMIT();
        buf ^= 1;
    }

    // ======== epilogue: register-resident stats + fp16 E bounce ========
    __syncthreads();
    __half* ebh  = reinterpret_cast<__half*>(smc);                 // [128][120] halves
    float* rmax2 = reinterpret_cast<float*>(smc + 30720);          // [128][2]
    float* psum2 = reinterpret_cast<float*>(smc + 30720 + 1024);   // [128][2]

    const int r = lane >> 2;   // 0..7
    const int q = lane & 3;    // 0..3

    float rmx[4];
    #pragma unroll
    for (int i = 0; i < 2; i++) {
        float m0 = -CUDART_INF_F, m1 = -CUDART_INF_F;
        #pragma unroll
        for (int j = 0; j < 7; j++) {
            m0 = fmaxf(m0, fmaxf(acc[i*7+j][0], acc[i*7+j][1]));
            m1 = fmaxf(m1, fmaxf(acc[i*7+j][2], acc[i*7+j][3]));
        }
        #pragma unroll
        for (int o = 1; o < 4; o <<= 1) {
            m0 = fmaxf(m0, __shfl_xor_sync(0xffffffffu, m0, o));
            m1 = fmaxf(m1, __shfl_xor_sync(0xffffffffu, m1, o));
        }
        rmx[i*2]   = m0;
        rmx[i*2+1] = m1;
    }
    if (q == 0) {
        #pragma unroll
        for (int k = 0; k < 4; k++) {
            int row = wm * 32 + (k >> 1) * 16 + (k & 1) * 8 + r;
            rmax2[row * 2 + wn] = rmx[k];
        }
    }
    __syncthreads();

    float frmx[4];
    #pragma unroll
    for (int k = 0; k < 4; k++) {
        int row = wm * 32 + (k >> 1) * 16 + (k & 1) * 8 + r;
        frmx[k] = fmaxf(rmax2[row * 2], rmax2[row * 2 + 1]);
    }

    float ps[4] = {0.f, 0.f, 0.f, 0.f};
    #pragma unroll
    for (int i = 0; i < 2; i++) {
        #pragma unroll
        for (int j = 0; j < 7; j++) {
            int col  = wn * 56 + j * 8 + q * 2;
            int row0 = wm * 32 + i * 16 + r;
            float e0 = __expf(acc[i*7+j][0] - frmx[i*2]);
            float e1 = __expf(acc[i*7+j][1] - frmx[i*2]);
            float e2 = __expf(acc[i*7+j][2] - frmx[i*2+1]);
            float e3 = __expf(acc[i*7+j][3] - frmx[i*2+1]);
            ps[i*2]   += e0 + e1;
            ps[i*2+1] += e2 + e3;
            __half2 h01 = __floats2half2_rn(e0, e1);
            __half2 h23 = __floats2half2_rn(e2, e3);
            *reinterpret_cast<__half2*>(ebh + row0 * G2_EPH + col)       = h01;
            *reinterpret_cast<__half2*>(ebh + (row0 + 8) * G2_EPH + col) = h23;
        }
    }
    #pragma unroll
    for (int k = 0; k < 4; k++)
        #pragma unroll
        for (int o = 1; o < 4; o <<= 1)
            ps[k] += __shfl_xor_sync(0xffffffffu, ps[k], o);
    if (q == 0) {
        #pragma unroll
        for (int k = 0; k < 4; k++) {
            int row = wm * 32 + (k >> 1) * 16 + (k & 1) * 8 + r;
            psum2[row * 2 + wn] = ps[k];
        }
    }
    __syncthreads();

    if (tid < 128 && n0 + tid < NPOS) {
        int o = (b * 7 + cbx) * NPOS + n0 + tid;
        g_pmax[o] = fmaxf(rmax2[tid * 2], rmax2[tid * 2 + 1]);
        g_psum[o] = psum2[tid * 2] + psum2[tid * 2 + 1];
    }

    #pragma unroll
    for (int i = 0; i < 7; i++) {
        int t = tid + i * 256;          // 0..1791
        int row = t / 14, cg = t % 14;
        if (n0 + row < NPOS) {
            uint4 v = *reinterpret_cast<const uint4*>(ebh + row * G2_EPH + cg * 8);
            *reinterpret_cast<uint4*>(
                g_E + ((size_t)b * NPOS + n0 + row) * NPOS + mb0 + cg * 8) = v;
        }
    }
}

// ===========================================================================
// colsum (vectorized, inline combine):
// a_bar[b][m] += sum_n E[n][m] * w[n][cb(m)]; thread handles 4 adjacent m.
// ===========================================================================
__global__ __launch_bounds__(196) void colsum_kernel()
{
    const int b  = blockIdx.z;
    const int n0 = blockIdx.y * 56;
    const int t  = threadIdx.x;          // 0..195
    const int m4 = t * 4;                // 0..780
    const int cbx = m4 / 112;            // 0..6

    __shared__ float sw[7][56];
    if (t < 56) {
        int n = n0 + t;
        float pm[7];
        float mx = -CUDART_INF_F;
        #pragma unroll
        for (int cb = 0; cb < 7; cb++) {
            pm[cb] = g_pmax[(b * 7 + cb) * NPOS + n];
            mx = fmaxf(mx, pm[cb]);
        }
        float s = 0.f;
        #pragma unroll
        for (int cb = 0; cb < 7; cb++)
            s += g_psum[(b * 7 + cb) * NPOS + n] * __expf(pm[cb] - mx);
        float inv = 1.f / (s * (float)NPOS);
        #pragma unroll
        for (int cb = 0; cb < 7; cb++)
            sw[cb][t] = __expf(pm[cb] - mx) * inv;
    }
    __syncthreads();

    const __half* __restrict__ Eb = g_E + ((size_t)b * NPOS + n0) * NPOS + m4;
    float a0 = 0.f, a1 = 0.f, a2 = 0.f, a3 = 0.f;
    #pragma unroll 8
    for (int j = 0; j < 56; j++) {
        uint2 v = *reinterpret_cast<const uint2*>(Eb + (size_t)j * NPOS);
        __half2 h01 = *reinterpret_cast<__half2*>(&v.x);
        __half2 h23 = *reinterpret_cast<__half2*>(&v.y);
        float2 f01 = __half22float2(h01);
        float2 f23 = __half22float2(h23);
        float w = sw[cbx][j];
        a0 = fmaf(f01.x, w, a0);
        a1 = fmaf(f01.y, w, a1);
        a2 = fmaf(f23.x, w, a2);
        a3 = fmaf(f23.y, w, a3);
    }
    atomicAdd(&g_abar[b * NPOS + m4 + 0], a0);
    atomicAdd(&g_abar[b * NPOS + m4 + 1], a1);
    atomicAdd(&g_abar[b * NPOS + m4 + 2], a2);
    atomicAdd(&g_abar[b * NPOS + m4 + 3], a3);
}

// xw[b][c] += sum_n Xt[b][n][c]*abar[n];  xbar[b][c] += sum_n Xt[b][n][c]/784
__global__ __launch_bounds__(256) void xw_kernel()
{
    const int b   = blockIdx.z;
    const int c0  = blockIdx.x * 512;
    const int n0  = blockIdx.y * 98;
    const int tid = threadIdx.x;

    __shared__ float sa[98];
    if (tid < 98) sa[tid] = g_abar[b * NPOS + n0 + tid];
    __syncthreads();

    const __half2* __restrict__ Xt2 = reinterpret_cast<const __half2*>(
        g_Xt + ((size_t)b * NPOS + n0) * CDIM + c0) + tid;

    float d0 = 0.f, d1 = 0.f, s0 = 0.f, s1 = 0.f;
    #pragma unroll 7
    for (int n = 0; n < 98; n++) {
        __half2 h = Xt2[(size_t)n * (CDIM / 2)];
        float2 f = __half22float2(h);
        float a = sa[n];
        d0 = fmaf(f.x, a, d0);
        d1 = fmaf(f.y, a, d1);
        s0 += f.x;
        s1 += f.y;
    }
    int c = c0 + tid * 2;
    atomicAdd(&g_xw[b * CDIM + c],       d0);
    atomicAdd(&g_xw[b * CDIM + c + 1],   d1);
    atomicAdd(&g_xbar[b * CDIM + c],     s0 * (1.f / (float)NPOS));
    atomicAdd(&g_xbar[b * CDIM + c + 1], s1 * (1.f / (float)NPOS));
}

__global__ __launch_bounds__(256) void ybar_kernel(const float* __restrict__ Wg,
                                                   const float* __restrict__ bg)
{
    const int b    = blockIdx.y;
    const int i    = blockIdx.x * 8 + (threadIdx.x >> 5);
    const int lane = threadIdx.x & 31;

    __shared__ float sx[CDIM];
    for (int k = threadIdx.x; k < CDIM; k += 256) sx[k] = g_xw[b * CDIM + k];
    __syncthreads();

    const float* __restrict__ w = Wg + (size_t)i * CDIM;
    float d = 0.f;
    for (int k = lane; k < CDIM; k += 32) d = fmaf(w[k], sx[k], d);
    #pragma unroll
    for (int o = 16; o; o >>= 1) d += __shfl_xor_sync(0xffffffffu, d, o);
    if (lane == 0) g_ybar[b * CI + i] = d + bg[i];
}

__global__ __launch_bounds__(256) void pooled_kernel(
    const float* __restrict__ Ww, const float* __restrict__ bw,
    const float* __restrict__ gamma, const float* __restrict__ beta,
    const float* __restrict__ bmean, const float* __restrict__ bvar)
{
    const int b    = blockIdx.y;
    const int c    = blockIdx.x * 8 + (threadIdx.x >> 5);
    const int lane = threadIdx.x & 31;

    __shared__ float sy[CI];
    for (int k = threadIdx.x; k < CI; k += 256) sy[k] = g_ybar[b * CI + k];
    __syncthreads();

    const float* __restrict__ w = Ww + (size_t)c * CI;
    float d = 0.f;
    for (int k = lane; k < CI; k += 32) d = fmaf(w[k], sy[k], d);
    #pragma unroll
    for (int o = 16; o; o >>= 1) d += __shfl_xor_sync(0xffffffffu, d, o);
    if (lane == 0) {
        float inv = gamma[c] * rsqrtf(bvar[c] + 1e-5f);
        g_pooled[b * CDIM + c] =
            inv * (d + bw[c]) + (beta[c] - bmean[c] * inv) + g_xbar[b * CDIM + c];
    }
}

__global__ __launch_bounds__(256) void h_kernel(const float* __restrict__ W1,
                                                const float* __restrict__ b1)
{
    const int b    = blockIdx.y;
    const int j    = blockIdx.x * 8 + (threadIdx.x >> 5);
    const int lane = threadIdx.x & 31;

    __shared__ float sp[CDIM];
    for (int k = threadIdx.x; k < CDIM; k += 256) sp[k] = g_pooled[b * CDIM + k];
    __syncthreads();

    const float* __restrict__ w = W1 + (size_t)j * CDIM;
    float d = 0.f;
    for (int k = lane; k < CDIM; k += 32) d = fmaf(w[k], sp[k], d);
    #pragma unroll
    for (int o = 16; o; o >>= 1) d += __shfl_xor_sync(0xffffffffu, d, o);
    if (lane == 0) g_h[b * CI + j] = d + b1[j];
}

__global__ __launch_bounds__(256) void out_kernel(const float* __restrict__ xface,
                                                  const float* __restrict__ W2,
                                                  const float* __restrict__ b2,
                                                  float* __restrict__ out)
{
    const int b = blockIdx.x;
    const int o = threadIdx.x >> 7;
    const int t = threadIdx.x & 127;

    float acc = 0.f;
    for (int k = t; k < CDIM; k += 128) {
        float v = (k < CI) ? g_h[b * CI + k] : xface[b * CI + (k - CI)];
        acc = fmaf(W2[o * CDIM + k], v, acc);
    }
    #pragma unroll
    for (int off = 16; off; off >>= 1) acc += __shfl_xor_sync(0xffffffffu, acc, off);

    __shared__ float sred[8];
    const int warp = threadIdx.x >> 5;
    if ((threadIdx.x & 31) == 0) sred[warp] = acc;
    __syncthreads();
    if (threadIdx.x == 0)
        out[b * 2 + 0] = sred[0] + sred[1] + sred[2] + sred[3] + b2[0];
    if (threadIdx.x == 128)
        out[b * 2 + 1] = sred[4] + sred[5] + sred[6] + sred[7] + b2[1];
}

// ===========================================================================
extern "C" void kernel_launch(void* const* d_in, const int* in_sizes, int n_in,
                              void* d_out, int out_size)
{
    const float* x_body = (const float*)d_in[0];
    const float* x_face = (const float*)d_in[1];
    const float* Wg     = (const float*)d_in[2];
    const float* bg     = (const float*)d_in[3];
    const float* Wth    = (const float*)d_in[4];
    const float* bth    = (const float*)d_in[5];
    const float* Wph    = (const float*)d_in[6];
    const float* bph    = (const float*)d_in[7];
    const float* Ww     = (const float*)d_in[8];
    const float* bw     = (const float*)d_in[9];
    const float* gamma  = (const float*)d_in[10];
    const float* beta   = (const float*)d_in[11];
    const float* bmean  = (const float*)d_in[12];
    const float* bvar   = (const float*)d_in[13];
    const float* W1     = (const float*)d_in[14];
    const float* b1     = (const float*)d_in[15];
    const float* W2     = (const float*)d_in[16];
    const float* b2     = (const float*)d_in[17];
    float* out = (float*)d_out;

    cudaFuncSetAttribute(gemm1_mma, cudaFuncAttributeMaxDynamicSharedMemorySize, G1_SMEM);
    cudaFuncSetAttribute(gemm2_mma, cudaFuncAttributeMaxDynamicSharedMemorySize, G2_SMEM);

    convert_W_kernel<<<(CDIM * CDIM) / 256, 256>>>(Wth, Wph);
    convert_X_kernel<<<dim3((NPOS + 63) / 64, CDIM / 64, BATCH), 256>>>(x_body);

    gemm1_mma<<<dim3(NPOS / 112, CDIM / 128, BATCH), 128, G1_SMEM>>>(bth, bph);
    gemm2_mma<<<dim3(NPOS / 112, (NPOS + 127) / 128, BATCH), 256, G2_SMEM>>>();

    colsum_kernel<<<dim3(1, 14, BATCH), 196>>>();
    xw_kernel<<<dim3(2, 8, BATCH), 256>>>();
    ybar_kernel<<<dim3(CI / 8, BATCH), 256>>>(Wg, bg);
    pooled_kernel<<<dim3(CDIM / 8, BATCH), 256>>>(Ww, bw, gamma, beta, bmean, bvar);
    h_kernel<<<dim3(CI / 8, BATCH), 256>>>(W1, b1);
    out_kernel<<<BATCH, 256>>>(x_face, W2, b2, out);
}